// round 3
// baseline (speedup 1.0000x reference)
#include <cuda_runtime.h>

// SharedRadialLinearTransform: out[n,s,a,m] = sum_r x[n,r,a,m] * W[group(a),r,s]
// x: [2048, 12, 20, 128] f32 (252 MB), out same. Memory-bound, AI = 3 FLOP/B.
// This round: Blackwell 256-bit vector ld/st (v8.f32) to halve transaction count
// and lengthen DRAM bursts. One thread per (n, a, m8-chunk of 8 floats).

constexpr int RAD = 12;
constexpr int ANG = 20;
constexpr int EMB = 128;
constexpr int NG  = 4;
constexpr int EMB8 = EMB / 8;           // 16 v8-chunks per (n,r,a) row
constexpr int STRIDEF = ANG * EMB;      // 2560 floats between r (or s) slices

__device__ __forceinline__ void ldg_v8(const float* p, float* v) {
    asm volatile("ld.global.nc.v8.f32 {%0,%1,%2,%3,%4,%5,%6,%7}, [%8];"
        : "=f"(v[0]), "=f"(v[1]), "=f"(v[2]), "=f"(v[3]),
          "=f"(v[4]), "=f"(v[5]), "=f"(v[6]), "=f"(v[7])
        : "l"(p));
}

__device__ __forceinline__ void stg_v8(float* p, const float* v) {
    asm volatile("st.global.cs.v8.f32 [%0], {%1,%2,%3,%4,%5,%6,%7,%8};"
        :: "l"(p),
           "f"(v[0]), "f"(v[1]), "f"(v[2]), "f"(v[3]),
           "f"(v[4]), "f"(v[5]), "f"(v[6]), "f"(v[7])
        : "memory");
}

__global__ __launch_bounds__(256, 2)   // cap at 128 regs -> 2 blocks/SM
void srlt_kernel(const float* __restrict__ x,
                 const float* __restrict__ W,
                 float* __restrict__ out)
{
    __shared__ float w[NG * RAD * RAD];   // 576 floats
    for (int i = threadIdx.x; i < NG * RAD * RAD; i += blockDim.x)
        w[i] = W[i];
    __syncthreads();

    int idx  = blockIdx.x * blockDim.x + threadIdx.x;
    int m8   = idx & (EMB8 - 1);   // 0..15  (16 lanes cover 512B; warp = 1KB)
    int tile = idx >> 4;           // (n, a)
    int a    = tile % ANG;
    int n    = tile / ANG;

    // group(a): sizes [1,3,6,10] -> 0 | 1-3 | 4-9 | 10-19
    int g = (a >= 10) ? 3 : (a >= 4) ? 2 : (a >= 1) ? 1 : 0;
    const float* __restrict__ wg = w + g * RAD * RAD;

    // 32-bit offsets (max index 62.9M < 2^31); 32B-aligned (m8*8 floats)
    int base = (n * RAD * ANG + a) * EMB + m8 * 8;
    const float* __restrict__ xp = x + base;
    float* __restrict__ op = out + base;

    float xv[RAD][8];
#pragma unroll
    for (int r = 0; r < RAD; r++)
        ldg_v8(xp + r * STRIDEF, xv[r]);

#pragma unroll
    for (int s = 0; s < RAD; s++) {
        float acc[8] = {0.f, 0.f, 0.f, 0.f, 0.f, 0.f, 0.f, 0.f};
#pragma unroll
        for (int r = 0; r < RAD; r++) {
            float wv = wg[r * RAD + s];   // broadcast LDS
#pragma unroll
            for (int k = 0; k < 8; k++)
                acc[k] = fmaf(xv[r][k], wv, acc[k]);
        }
        stg_v8(op + s * STRIDEF, acc);
    }
}

extern "C" void kernel_launch(void* const* d_in, const int* in_sizes, int n_in,
                              void* d_out, int out_size)
{
    const float* x = (const float*)d_in[0];
    const float* W = (const float*)d_in[1];
    float* out = (float*)d_out;

    int n_nodes = in_sizes[0] / (RAD * ANG * EMB);
    int total_threads = n_nodes * ANG * EMB8;   // 655,360 for n_nodes=2048

    int block = 256;
    int grid = (total_threads + block - 1) / block;  // 2560, exact
    srlt_kernel<<<grid, block>>>(x, W, out);
}

// round 4
// speedup vs baseline: 1.1608x; 1.1608x over previous
#include <cuda_runtime.h>

// SharedRadialLinearTransform: out[n,s,a,m] = sum_r x[n,r,a,m] * W[group(a),r,s]
// x: [2048, 12, 20, 128] f32 (252 MB), out same. Memory-bound, AI = 3 FLOP/B.
// R4: revert to float4 (v8 regressed: cracked wavefronts + spills at 128-reg cap);
// raise occupancy to 3 blocks/SM via launch_bounds reg budget (93 -> <=84).

constexpr int RAD = 12;
constexpr int ANG = 20;
constexpr int EMB = 128;
constexpr int NG  = 4;
constexpr int EMB4 = EMB / 4;          // 32 float4 per (n,r,a) row
constexpr int STRIDE4 = ANG * EMB4;    // 640: float4 stride between r (or s) slices

__global__ __launch_bounds__(256, 3)   // reg budget 84 -> 3 blocks/SM
void srlt_kernel(const float4* __restrict__ x,
                 const float*  __restrict__ W,
                 float4* __restrict__ out)
{
    __shared__ float w[NG * RAD * RAD];   // 576 floats
    for (int i = threadIdx.x; i < NG * RAD * RAD; i += blockDim.x)
        w[i] = W[i];
    __syncthreads();

    // one thread per (n, a, m4); grid sized exactly, no bounds check needed
    int idx  = blockIdx.x * blockDim.x + threadIdx.x;
    int m4   = idx & (EMB4 - 1);   // 0..31  (warp covers 512B contiguous)
    int tile = idx >> 5;           // (n, a)
    int a    = tile % ANG;
    int n    = tile / ANG;

    // group(a): sizes [1,3,6,10] -> 0 | 1-3 | 4-9 | 10-19
    int g = (a >= 10) ? 3 : (a >= 4) ? 2 : (a >= 1) ? 1 : 0;
    const float* __restrict__ wg = w + g * RAD * RAD;

    // 32-bit base index; r/s offsets are compile-time immediates so ptxas
    // emits LDG/STG [base + imm] off one base register pair each.
    int base = (n * RAD * ANG + a) * EMB4 + m4;
    const float4* __restrict__ xp = x + base;
    float4* __restrict__ op = out + base;

    float4 xv[RAD];
#pragma unroll
    for (int r = 0; r < RAD; r++)
        xv[r] = __ldcs(xp + r * STRIDE4);   // streaming load, evict-first

#pragma unroll
    for (int s = 0; s < RAD; s++) {
        float4 acc = make_float4(0.f, 0.f, 0.f, 0.f);
#pragma unroll
        for (int r = 0; r < RAD; r++) {
            float wv = wg[r * RAD + s];     // broadcast LDS, conflict-free
            acc.x = fmaf(xv[r].x, wv, acc.x);
            acc.y = fmaf(xv[r].y, wv, acc.y);
            acc.z = fmaf(xv[r].z, wv, acc.z);
            acc.w = fmaf(xv[r].w, wv, acc.w);
        }
        __stcs(op + s * STRIDE4, acc);      // streaming store
    }
}

extern "C" void kernel_launch(void* const* d_in, const int* in_sizes, int n_in,
                              void* d_out, int out_size)
{
    const float4* x = (const float4*)d_in[0];
    const float*  W = (const float*)d_in[1];
    float4* out = (float4*)d_out;

    int n_nodes = in_sizes[0] / (RAD * ANG * EMB);
    int total_threads = n_nodes * ANG * EMB4;   // 1,310,720 for n_nodes=2048

    int block = 256;
    int grid = (total_threads + block - 1) / block;  // 5120, exact
    srlt_kernel<<<grid, block>>>(x, W, out);
}

// round 5
// speedup vs baseline: 1.2155x; 1.0471x over previous
#include <cuda_runtime.h>

// SharedRadialLinearTransform: out[n,s,a,m] = sum_r x[n,r,a,m] * W[group(a),r,s]
// x: [2048, 12, 20, 128] f32 (252 MB), out same. Memory-bound, AI = 3 FLOP/B.
// R5: inverted loop structure — accumulators resident (48 regs), each loaded
// xv consumed immediately. Fits 84-reg budget (3 blocks/SM) WITHOUT the spills
// that killed R4 (same occupancy, but L1/alu spill overhead gone).

constexpr int RAD = 12;
constexpr int ANG = 20;
constexpr int EMB = 128;
constexpr int NG  = 4;
constexpr int EMB4 = EMB / 4;          // 32 float4 per (n,r,a) row
constexpr int STRIDE4 = ANG * EMB4;    // 640: float4 stride between r (or s) slices

__global__ __launch_bounds__(256, 3)   // reg budget 84 -> 3 blocks/SM
void srlt_kernel(const float4* __restrict__ x,
                 const float*  __restrict__ W,
                 float4* __restrict__ out)
{
    __shared__ float w[NG * RAD * RAD];   // 576 floats
    for (int i = threadIdx.x; i < NG * RAD * RAD; i += blockDim.x)
        w[i] = W[i];
    __syncthreads();

    // one thread per (n, a, m4); grid sized exactly, no bounds check needed
    int idx  = blockIdx.x * blockDim.x + threadIdx.x;
    int m4   = idx & (EMB4 - 1);   // 0..31  (warp covers 512B contiguous)
    int tile = idx >> 5;           // (n, a)
    int a    = tile % ANG;
    int n    = tile / ANG;

    // group(a): sizes [1,3,6,10] -> 0 | 1-3 | 4-9 | 10-19
    int g = (a >= 10) ? 3 : (a >= 4) ? 2 : (a >= 1) ? 1 : 0;
    const float* __restrict__ wg = w + g * RAD * RAD;

    int base = (n * RAD * ANG + a) * EMB4 + m4;
    const float4* __restrict__ xp = x + base;
    float4* __restrict__ op = out + base;

    // Accumulators resident; loads consumed immediately (short live range).
    float4 acc[RAD];
#pragma unroll
    for (int s = 0; s < RAD; s++)
        acc[s] = make_float4(0.f, 0.f, 0.f, 0.f);

#pragma unroll
    for (int r = 0; r < RAD; r++) {
        float4 xr = __ldcs(xp + r * STRIDE4);
#pragma unroll
        for (int s = 0; s < RAD; s++) {
            float wv = wg[r * RAD + s];   // warp-uniform broadcast LDS
            acc[s].x = fmaf(xr.x, wv, acc[s].x);
            acc[s].y = fmaf(xr.y, wv, acc[s].y);
            acc[s].z = fmaf(xr.z, wv, acc[s].z);
            acc[s].w = fmaf(xr.w, wv, acc[s].w);
        }
    }

#pragma unroll
    for (int s = 0; s < RAD; s++)
        __stcs(op + s * STRIDE4, acc[s]);

}

extern "C" void kernel_launch(void* const* d_in, const int* in_sizes, int n_in,
                              void* d_out, int out_size)
{
    const float4* x = (const float4*)d_in[0];
    const float*  W = (const float*)d_in[1];
    float4* out = (float4*)d_out;

    int n_nodes = in_sizes[0] / (RAD * ANG * EMB);
    int total_threads = n_nodes * ANG * EMB4;   // 1,310,720 for n_nodes=2048

    int block = 256;
    int grid = (total_threads + block - 1) / block;  // 5120, exact
    srlt_kernel<<<grid, block>>>(x, W, out);
}